// round 9
// baseline (speedup 1.0000x reference)
#include <cuda_runtime.h>
#include <math.h>

// Quaternion LSTM: T=128, B=64, F=512, H=1024.
// Round 9: Karatsuba (12-mult, FLOPs x0.75, signs validated in R8) +
// balanced static tiling: 148 CTAs x 512 thr (1/SM), 384 tiles of 64x128x64,
// max 3 tiles/SM. 4x4 micro w/ float4 smem reads. Vectorized gemm_in B loads.

#define T_ 128
#define B_ 64
#define Fdim 512
#define H_ 1024
#define N4 (4 * H_)          // 4096
#define FO (Fdim + 1)        // 513
#define NCTA 148
#define NTILES 384           // 4 ksplit x 6 combos x 16 coltiles

// ---- scratch ----
__device__ float g_Wcat[(size_t)Fdim * N4];            //  8 MB
__device__ float g_bias4[N4];
__device__ float g_Uq[6 * 256 * 2048];                 // 12.6 MB combined U
__device__ float g_G[(size_t)T_ * B_ * N4];            // 128 MB (pre-gates)
__device__ float g_m[4 * 6 * B_ * 2048];               // 12.6 MB partials
__device__ float g_h[B_ * H_];
__device__ float g_c[B_ * H_];
__device__ float g_Hbuf[(size_t)T_ * B_ * H_];         // 32 MB
__device__ unsigned g_cnt;
__device__ volatile unsigned g_gen;

__device__ const float c_sgn[16] = {
    1.f, -1.f, -1.f, -1.f,
    1.f,  1.f, -1.f,  1.f,
    1.f,  1.f,  1.f, -1.f,
    1.f, -1.f,  1.f,  1.f
};

// ---------------- init ----------------
__global__ void init_state() {
    int idx = blockIdx.x * blockDim.x + threadIdx.x;
    if (idx < B_ * H_) { g_h[idx] = 0.f; g_c[idx] = 0.f; }
    if (idx == 0) { g_cnt = 0; g_gen = 0; }
}

// ---------------- builds ----------------
__global__ void build_W(const float* __restrict__ wf, const float* __restrict__ wi,
                        const float* __restrict__ wo, const float* __restrict__ wc) {
    int idx = blockIdx.x * blockDim.x + threadIdx.x;
    if (idx >= Fdim * N4) return;
    int row  = idx / N4;
    int col  = idx % N4;
    int gate = col / H_;
    int cj   = col % H_;
    int rb = row / (Fdim / 4), a = row % (Fdim / 4);
    int cb = cj / (H_ / 4),    b = cj % (H_ / 4);
    const float* w = (gate == 0) ? wf : (gate == 1) ? wi : (gate == 2) ? wo : wc;
    g_Wcat[idx] = c_sgn[cb * 4 + rb] *
                  w[((size_t)(rb ^ cb) * (Fdim / 4) + a) * (H_ / 4) + b];
}

// Combined U for the 12-mult scheme (validated R8).
//  c0: u0 , u2   c1: u1 , u3   c2: u0+u1 , u3-u2
//  c3: u2 , u0   c4: u3 , u1   c5: u3-u2 , u0+u1
__global__ void build_Uq(const float* __restrict__ uf, const float* __restrict__ ui,
                         const float* __restrict__ uo, const float* __restrict__ uc) {
    int idx = blockIdx.x * blockDim.x + threadIdx.x;
    if (idx >= 6 * 256 * 2048) return;
    int c   = idx / (256 * 2048);
    int rem = idx % (256 * 2048);
    int k   = rem / 2048;
    int col = rem % 2048;
    int g   = col >> 9;
    int p   = (col >> 8) & 1;
    int n4  = col & 255;
    const float* u = (g == 0) ? uf : (g == 1) ? ui : (g == 2) ? uo : uc;
    size_t base = (size_t)k * 256 + n4;
    float u0 = u[base], u1 = u[base + 65536], u2 = u[base + 131072], u3 = u[base + 196608];
    float v;
    if (c == 0) v = p ? u2 : u0;
    else if (c == 1) v = p ? u3 : u1;
    else if (c == 2) v = p ? (u3 - u2) : (u0 + u1);
    else if (c == 3) v = p ? u0 : u2;
    else if (c == 4) v = p ? u1 : u3;
    else             v = p ? (u0 + u1) : (u3 - u2);
    g_Uq[idx] = v;
}

__global__ void build_bias(const float* __restrict__ bf, const float* __restrict__ bi,
                           const float* __restrict__ bo, const float* __restrict__ bc) {
    int idx = blockIdx.x * blockDim.x + threadIdx.x;
    if (idx >= N4) return;
    int gate = idx / H_, j = idx % H_;
    const float* b = (gate == 0) ? bf : (gate == 1) ? bi : (gate == 2) ? bo : bc;
    g_bias4[idx] = b[j];
}

// ---------------- generic fp32 GEMM (128x128 tile, 8x8 micro) ----------------
__device__ __forceinline__ void gemm_body(const float* __restrict__ A,
                                          const float* __restrict__ Bm,
                                          const float* __restrict__ bias,
                                          float* __restrict__ C,
                                          int M, int N, int K) {
    const int BM = 128, BN = 128, BK = 16;
    __shared__ float As[BK][BM];
    __shared__ float Bs[BK][BN];
    int tid = threadIdx.x;
    int tx = tid % 16, ty = tid / 16;
    int rowBase = blockIdx.y * BM;
    int colBase = blockIdx.x * BN;
    bool fullN = ((N & 3) == 0) && (colBase + BN <= N);
    float acc[8][8];
    #pragma unroll
    for (int i = 0; i < 8; i++)
        #pragma unroll
        for (int j = 0; j < 8; j++) acc[i][j] = 0.f;

    for (int k0 = 0; k0 < K; k0 += BK) {
        #pragma unroll
        for (int i = 0; i < 2; i++) {
            int lin = tid + i * 256;
            int r = lin >> 2, c4 = (lin & 3) * 4;
            float4 v = *reinterpret_cast<const float4*>(
                &A[(size_t)(rowBase + r) * K + k0 + c4]);
            As[c4 + 0][r] = v.x;
            As[c4 + 1][r] = v.y;
            As[c4 + 2][r] = v.z;
            As[c4 + 3][r] = v.w;
        }
        if (fullN) {
            #pragma unroll
            for (int i = 0; i < 2; i++) {
                int lin = tid + i * 256;
                int kk = lin >> 5, c4 = (lin & 31) * 4;
                float4 v = *reinterpret_cast<const float4*>(
                    &Bm[(size_t)(k0 + kk) * N + colBase + c4]);
                *reinterpret_cast<float4*>(&Bs[kk][c4]) = v;
            }
        } else {
            #pragma unroll
            for (int i = 0; i < 8; i++) {
                int lin = tid + i * 256;
                int kk = lin >> 7, n = lin & 127;
                int gn = colBase + n;
                float v = 0.f;
                if (gn < N) v = Bm[(size_t)(k0 + kk) * N + gn];
                Bs[kk][n] = v;
            }
        }
        __syncthreads();
        #pragma unroll
        for (int kk = 0; kk < BK; kk++) {
            float a[8], b[8];
            float4 a0 = *reinterpret_cast<const float4*>(&As[kk][ty * 8]);
            float4 a1 = *reinterpret_cast<const float4*>(&As[kk][ty * 8 + 4]);
            float4 b0 = *reinterpret_cast<const float4*>(&Bs[kk][tx * 8]);
            float4 b1 = *reinterpret_cast<const float4*>(&Bs[kk][tx * 8 + 4]);
            a[0]=a0.x; a[1]=a0.y; a[2]=a0.z; a[3]=a0.w;
            a[4]=a1.x; a[5]=a1.y; a[6]=a1.z; a[7]=a1.w;
            b[0]=b0.x; b[1]=b0.y; b[2]=b0.z; b[3]=b0.w;
            b[4]=b1.x; b[5]=b1.y; b[6]=b1.z; b[7]=b1.w;
            #pragma unroll
            for (int i = 0; i < 8; i++)
                #pragma unroll
                for (int j = 0; j < 8; j++)
                    acc[i][j] += a[i] * b[j];
        }
        __syncthreads();
    }
    #pragma unroll
    for (int i = 0; i < 8; i++) {
        int gm = rowBase + ty * 8 + i;
        if (gm >= M) continue;
        #pragma unroll
        for (int j = 0; j < 8; j++) {
            int gn = colBase + tx * 8 + j;
            if (gn >= N) continue;
            float v = acc[i][j];
            if (bias) v += bias[gn];
            C[(size_t)gm * N + gn] = v;
        }
    }
}

__global__ __launch_bounds__(256) void gemm_in(const float* __restrict__ x) {
    gemm_body(x, g_Wcat, g_bias4, g_G, T_ * B_, N4, Fdim);
}
__global__ __launch_bounds__(256) void gemm_out(const float* __restrict__ fw,
                                                const float* __restrict__ fb,
                                                float* __restrict__ out) {
    gemm_body(g_Hbuf, fw, fb, out, T_ * B_, FO, H_);
}

// ---------------- grid barrier (148 CTAs, 1/SM) ----------------
__device__ __forceinline__ void grid_barrier() {
    __syncthreads();
    __threadfence();
    if (threadIdx.x == 0) {
        unsigned gen = g_gen;
        unsigned prev = atomicAdd(&g_cnt, 1u);
        if (prev == NCTA - 1) {
            g_cnt = 0;
            __threadfence();
            g_gen = gen + 1;
        } else {
            while (g_gen == gen) { }
        }
    }
    __syncthreads();
    __threadfence();
}

// ---------------- persistent recurrence ----------------
// Phase 1: 384 static tiles (64x128x64), <=3 per CTA/SM. 512 thr, 4x4 micro.
// Phase 2: Karatsuba combine (sum 4 ksplits) + gates + update (4096 threads).
__global__ __launch_bounds__(512, 1) void recurrence() {
    __shared__ float As[16][68];
    __shared__ float Bs[16][132];
    int tid = threadIdx.x;
    int tx = tid & 31, ty = tid >> 5;       // 32 x 16 grid, micro 4 rows x 4 cols
    const float4* h4 = reinterpret_cast<const float4*>(g_h);
    int gtid = blockIdx.x * 512 + tid;

    for (int t = 0; t < T_; t++) {
        // ======== phase 1: 12-mult partials, static tiles
        #pragma unroll 1
        for (int it = 0; it < 3; it++) {
            int tl = blockIdx.x + NCTA * it;
            if (tl < NTILES) {
                int nt   = tl & 15;
                int rest = tl >> 4;
                int c    = rest % 6;
                int s    = rest / 6;           // 0..3
                int kbase = s * 64;
                int colBase = nt * 128;
                int base1 = (c == 0 || c == 2) ? 0 : (c == 1) ? 256
                          : (c == 3 || c == 5) ? 512 : 768;
                int base2 = (c == 2) ? 256 : (c == 5) ? 768 : -1;

                float acc[4][4];
                #pragma unroll
                for (int i = 0; i < 4; i++)
                    #pragma unroll
                    for (int j = 0; j < 4; j++) acc[i][j] = 0.f;

                #pragma unroll
                for (int k0 = 0; k0 < 64; k0 += 16) {
                    if (tid < 256) {   // A: 64x16, combo formed, transposed
                        int r = tid >> 2, kq = (tid & 3) * 4;
                        int off = base1 + kbase + k0 + kq;
                        float4 v = h4[(r * H_ + off) >> 2];
                        if (base2 >= 0) {
                            float4 w = h4[(r * H_ + off + (base2 - base1)) >> 2];
                            v.x += w.x; v.y += w.y; v.z += w.z; v.w += w.w;
                        }
                        As[kq + 0][r] = v.x;
                        As[kq + 1][r] = v.y;
                        As[kq + 2][r] = v.z;
                        As[kq + 3][r] = v.w;
                    }
                    {   // B: 16x128 = 512 float4, one per thread
                        int kk = tid >> 5, cq = (tid & 31) * 4;
                        float4 v = *reinterpret_cast<const float4*>(
                            &g_Uq[((size_t)c * 256 + kbase + k0 + kk) * 2048 + colBase + cq]);
                        *reinterpret_cast<float4*>(&Bs[kk][cq]) = v;
                    }
                    __syncthreads();
                    #pragma unroll
                    for (int kk = 0; kk < 16; kk++) {
                        float4 a = *reinterpret_cast<const float4*>(&As[kk][ty * 4]);
                        float4 b = *reinterpret_cast<const float4*>(&Bs[kk][tx * 4]);
                        float av[4] = {a.x, a.y, a.z, a.w};
                        float bv[4] = {b.x, b.y, b.z, b.w};
                        #pragma unroll
                        for (int i = 0; i < 4; i++)
                            #pragma unroll
                            for (int j = 0; j < 4; j++)
                                acc[i][j] += av[i] * bv[j];
                    }
                    __syncthreads();
                }
                float* mout = g_m + ((size_t)(s * 6 + c) * B_) * 2048;
                #pragma unroll
                for (int i = 0; i < 4; i++) {
                    int row = ty * 4 + i;
                    float4 v = {acc[i][0], acc[i][1], acc[i][2], acc[i][3]};
                    *reinterpret_cast<float4*>(
                        &mout[(size_t)row * 2048 + colBase + tx * 4]) = v;
                }
            }
        }

        grid_barrier();

        // ======== phase 2: combine + update (4096 threads: b x n4-quad)
        if (gtid < 4096) {
            int b   = gtid >> 6;
            int n4q = (gtid & 63) * 4;
            const float4* m4 = reinterpret_cast<const float4*>(g_m);
            const float4* G4 = reinterpret_cast<const float4*>(
                g_G + (size_t)((size_t)t * B_ + b) * N4);
            // MM(c,p,g): sum of 4 ksplit partials (R8 formulas, s extended to 4)
            #define MM(c, p, g) ({                                               \
                float4 _r = m4[((size_t)((0 * 6 + (c)) * B_ + b)) * 512 + ((g) * 2 + (p)) * 64 + (n4q >> 2)]; \
                float4 _1 = m4[((size_t)((1 * 6 + (c)) * B_ + b)) * 512 + ((g) * 2 + (p)) * 64 + (n4q >> 2)]; \
                float4 _2 = m4[((size_t)((2 * 6 + (c)) * B_ + b)) * 512 + ((g) * 2 + (p)) * 64 + (n4q >> 2)]; \
                float4 _3 = m4[((size_t)((3 * 6 + (c)) * B_ + b)) * 512 + ((g) * 2 + (p)) * 64 + (n4q >> 2)]; \
                make_float4(_r.x + _1.x + _2.x + _3.x, _r.y + _1.y + _2.y + _3.y, \
                            _r.z + _1.z + _2.z + _3.z, _r.w + _1.w + _2.w + _3.w); })
            #pragma unroll
            for (int o = 0; o < 4; o++) {
                float4 pre[4];
                #pragma unroll
                for (int g = 0; g < 4; g++) {
                    float4 r = G4[g * 256 + o * 64 + (n4q >> 2)];
                    float4 q;
                    if (o == 0) {            // M00 - M10 - M30 - M40
                        float4 a = MM(0,0,g), b2 = MM(1,0,g), c2 = MM(3,0,g), d = MM(4,0,g);
                        q.x = a.x - b2.x - c2.x - d.x; q.y = a.y - b2.y - c2.y - d.y;
                        q.z = a.z - b2.z - c2.z - d.z; q.w = a.w - b2.w - c2.w - d.w;
                    } else if (o == 1) {     // M20 - M00 - M10 - M50 - M30 + M40
                        float4 a = MM(2,0,g), b2 = MM(0,0,g), c2 = MM(1,0,g),
                               d = MM(5,0,g), e = MM(3,0,g), f = MM(4,0,g);
                        q.x = a.x - b2.x - c2.x - d.x - e.x + f.x;
                        q.y = a.y - b2.y - c2.y - d.y - e.y + f.y;
                        q.z = a.z - b2.z - c2.z - d.z - e.z + f.z;
                        q.w = a.w - b2.w - c2.w - d.w - e.w + f.w;
                    } else if (o == 2) {     // M31 - M41 + M01 + M11
                        float4 a = MM(3,1,g), b2 = MM(4,1,g), c2 = MM(0,1,g), d = MM(1,1,g);
                        q.x = a.x - b2.x + c2.x + d.x; q.y = a.y - b2.y + c2.y + d.y;
                        q.z = a.z - b2.z + c2.z + d.z; q.w = a.w - b2.w + c2.w + d.w;
                    } else {                 // M51 - M31 - M41 + M21 + M01 - M11
                        float4 a = MM(5,1,g), b2 = MM(3,1,g), c2 = MM(4,1,g),
                               d = MM(2,1,g), e = MM(0,1,g), f = MM(1,1,g);
                        q.x = a.x - b2.x - c2.x + d.x + e.x - f.x;
                        q.y = a.y - b2.y - c2.y + d.y + e.y - f.y;
                        q.z = a.z - b2.z - c2.z + d.z + e.z - f.z;
                        q.w = a.w - b2.w - c2.w + d.w + e.w - f.w;
                    }
                    pre[g] = make_float4(r.x + q.x, r.y + q.y, r.z + q.z, r.w + q.w);
                }
                size_t col = (size_t)b * H_ + o * 256 + n4q;
                float4 cprev = *reinterpret_cast<const float4*>(&g_c[col]);
                float fv[4] = {pre[0].x, pre[0].y, pre[0].z, pre[0].w};
                float iv[4] = {pre[1].x, pre[1].y, pre[1].z, pre[1].w};
                float ov[4] = {pre[2].x, pre[2].y, pre[2].z, pre[2].w};
                float av[4] = {pre[3].x, pre[3].y, pre[3].z, pre[3].w};
                float cp[4] = {cprev.x, cprev.y, cprev.z, cprev.w};
                float cnv[4], hnv[4];
                #pragma unroll
                for (int q2 = 0; q2 < 4; q2++) {
                    float ff = 1.f / (1.f + expf(-fv[q2]));
                    float ii = 1.f / (1.f + expf(-iv[q2]));
                    float oo = 1.f / (1.f + expf(-ov[q2]));
                    float cc = ii * tanhf(av[q2]) + ff * cp[q2];
                    cnv[q2] = cc;
                    hnv[q2] = oo * tanhf(cc);
                }
                float4 cn = {cnv[0], cnv[1], cnv[2], cnv[3]};
                float4 hn = {hnv[0], hnv[1], hnv[2], hnv[3]};
                *reinterpret_cast<float4*>(&g_c[col]) = cn;
                *reinterpret_cast<float4*>(&g_h[col]) = hn;
                *reinterpret_cast<float4*>(&g_Hbuf[(size_t)t * B_ * H_ + col]) = hn;
            }
            #undef MM
        }

        grid_barrier();
    }
}

// ---------------- launch ----------------
extern "C" void kernel_launch(void* const* d_in, const int* in_sizes, int n_in,
                              void* d_out, int out_size) {
    const float* x    = (const float*)d_in[0];
    const float* wfxw = (const float*)d_in[1];
    const float* wfxb = (const float*)d_in[2];
    const float* wixw = (const float*)d_in[3];
    const float* wixb = (const float*)d_in[4];
    const float* woxw = (const float*)d_in[5];
    const float* woxb = (const float*)d_in[6];
    const float* wcxw = (const float*)d_in[7];
    const float* wcxb = (const float*)d_in[8];
    const float* ufhw = (const float*)d_in[9];
    const float* uihw = (const float*)d_in[10];
    const float* uohw = (const float*)d_in[11];
    const float* uchw = (const float*)d_in[12];
    const float* fcow = (const float*)d_in[13];
    const float* fcob = (const float*)d_in[14];
    float* out = (float*)d_out;

    init_state<<<(B_ * H_ + 255) / 256, 256>>>();
    build_W<<<(Fdim * N4 + 255) / 256, 256>>>(wfxw, wixw, woxw, wcxw);
    build_bias<<<(N4 + 255) / 256, 256>>>(wfxb, wixb, woxb, wcxb);
    build_Uq<<<(6 * 256 * 2048 + 255) / 256, 256>>>(ufhw, uihw, uohw, uchw);

    {   // input projections: G = x @ Wcat + bias (vectorized B loads, N=4096)
        dim3 grid(N4 / 128, (T_ * B_) / 128);
        gemm_in<<<grid, 256>>>(x);
    }

    recurrence<<<NCTA, 512>>>();

    {   // output projection: out = Hbuf @ fco_w + fco_b
        dim3 grid((FO + 127) / 128, (T_ * B_) / 128);
        gemm_out<<<grid, 256>>>(fcow, fcob, out);
    }
}

// round 10
// speedup vs baseline: 1.1581x; 1.1581x over previous
#include <cuda_runtime.h>
#include <math.h>

// Quaternion LSTM: T=128, B=64, F=512, H=1024.
// Round 10: R7 (best, 5042us) + three targeted fixes:
//   1) two-level grid barrier (8 padded counters + final) — shorter drain
//   2) update phase spread across ALL 256 CTAs (was: CTAs 0-63 only)
//   3) vectorized gemm_in B-tile loads (fullN float4 path)
// GEMM / update math bit-identical to R7.

#define T_ 128
#define B_ 64
#define Fdim 512
#define H_ 1024
#define N4 (4 * H_)          // 4096
#define FO (Fdim + 1)        // 513
#define SPLITK 8
#define KCHUNK (H_ / SPLITK) // 128
#define NCTA 256
#define NGRP 8
#define GRPSZ (NCTA / NGRP)  // 32

// ---- scratch (static device globals: allocation-free) ----
__device__ float g_Wcat[(size_t)Fdim * N4];            //  8 MB
__device__ float g_bias4[N4];
__device__ float g_Ucat[(size_t)H_ * N4];              // 16 MB
__device__ float g_G[(size_t)T_ * B_ * N4];            // 128 MB (pre-gates)
__device__ float g_preK[(size_t)SPLITK * B_ * N4];     //  8 MB
__device__ float g_h[B_ * H_];
__device__ float g_c[B_ * H_];
__device__ float g_Hbuf[(size_t)T_ * B_ * H_];         // 32 MB

// two-level barrier state (counters padded to separate 128B lines)
__device__ unsigned g_cnt1[NGRP * 32];
__device__ unsigned g_cnt2;
__device__ volatile unsigned g_gen;

__device__ const float c_sgn[16] = {
    1.f, -1.f, -1.f, -1.f,
    1.f,  1.f, -1.f,  1.f,
    1.f,  1.f,  1.f, -1.f,
    1.f, -1.f,  1.f,  1.f
};

// ---------------- init ----------------
__global__ void init_state() {
    int idx = blockIdx.x * blockDim.x + threadIdx.x;
    if (idx < B_ * H_) { g_h[idx] = 0.f; g_c[idx] = 0.f; }
    if (idx < NGRP * 32) g_cnt1[idx] = 0;
    if (idx == 0) { g_cnt2 = 0; g_gen = 0; }
}

// ---------------- build Hamilton matrices ----------------
__global__ void build_W(const float* __restrict__ wf, const float* __restrict__ wi,
                        const float* __restrict__ wo, const float* __restrict__ wc) {
    int idx = blockIdx.x * blockDim.x + threadIdx.x;
    if (idx >= Fdim * N4) return;
    int row  = idx / N4;
    int col  = idx % N4;
    int gate = col / H_;
    int cj   = col % H_;
    int rb = row / (Fdim / 4), a = row % (Fdim / 4);
    int cb = cj / (H_ / 4),    b = cj % (H_ / 4);
    const float* w = (gate == 0) ? wf : (gate == 1) ? wi : (gate == 2) ? wo : wc;
    g_Wcat[idx] = c_sgn[cb * 4 + rb] *
                  w[((size_t)(rb ^ cb) * (Fdim / 4) + a) * (H_ / 4) + b];
}

__global__ void build_U(const float* __restrict__ uf, const float* __restrict__ ui,
                        const float* __restrict__ uo, const float* __restrict__ uc) {
    int idx = blockIdx.x * blockDim.x + threadIdx.x;
    if (idx >= H_ * N4) return;
    int row  = idx / N4;
    int col  = idx % N4;
    int gate = col / H_;
    int cj   = col % H_;
    int rb = row / (H_ / 4), a = row % (H_ / 4);
    int cb = cj / (H_ / 4),  b = cj % (H_ / 4);
    const float* w = (gate == 0) ? uf : (gate == 1) ? ui : (gate == 2) ? uo : uc;
    g_Ucat[idx] = c_sgn[cb * 4 + rb] *
                  w[((size_t)(rb ^ cb) * (H_ / 4) + a) * (H_ / 4) + b];
}

__global__ void build_bias(const float* __restrict__ bf, const float* __restrict__ bi,
                           const float* __restrict__ bo, const float* __restrict__ bc) {
    int idx = blockIdx.x * blockDim.x + threadIdx.x;
    if (idx >= N4) return;
    int gate = idx / H_, j = idx % H_;
    const float* b = (gate == 0) ? bf : (gate == 1) ? bi : (gate == 2) ? bo : bc;
    g_bias4[idx] = b[j];
}

// ---------------- generic fp32 GEMM (128x128 tile, 8x8 microtile) ----------------
__device__ __forceinline__ void gemm_body(const float* __restrict__ A,
                                          const float* __restrict__ Bm,
                                          const float* __restrict__ bias,
                                          float* __restrict__ C,
                                          int M, int N, int K) {
    const int BM = 128, BN = 128, BK = 16;
    __shared__ float As[BK][BM];
    __shared__ float Bs[BK][BN];
    int tid = threadIdx.x;
    int tx = tid % 16, ty = tid / 16;
    int rowBase = blockIdx.y * BM;
    int colBase = blockIdx.x * BN;
    bool fullN = ((N & 3) == 0) && (colBase + BN <= N);
    float acc[8][8];
    #pragma unroll
    for (int i = 0; i < 8; i++)
        #pragma unroll
        for (int j = 0; j < 8; j++) acc[i][j] = 0.f;

    for (int k0 = 0; k0 < K; k0 += BK) {
        #pragma unroll
        for (int i = 0; i < 2; i++) {
            int lin = tid + i * 256;
            int r = lin >> 2, c4 = (lin & 3) * 4;
            float4 v = *reinterpret_cast<const float4*>(
                &A[(size_t)(rowBase + r) * K + k0 + c4]);
            As[c4 + 0][r] = v.x;
            As[c4 + 1][r] = v.y;
            As[c4 + 2][r] = v.z;
            As[c4 + 3][r] = v.w;
        }
        if (fullN) {
            #pragma unroll
            for (int i = 0; i < 2; i++) {
                int lin = tid + i * 256;
                int kk = lin >> 5, c4 = (lin & 31) * 4;
                float4 v = *reinterpret_cast<const float4*>(
                    &Bm[(size_t)(k0 + kk) * N + colBase + c4]);
                *reinterpret_cast<float4*>(&Bs[kk][c4]) = v;
            }
        } else {
            #pragma unroll
            for (int i = 0; i < 8; i++) {
                int lin = tid + i * 256;
                int kk = lin >> 7, n = lin & 127;
                int gn = colBase + n;
                float v = 0.f;
                if (gn < N) v = Bm[(size_t)(k0 + kk) * N + gn];
                Bs[kk][n] = v;
            }
        }
        __syncthreads();
        #pragma unroll
        for (int kk = 0; kk < BK; kk++) {
            float a[8], b[8];
            float4 a0 = *reinterpret_cast<const float4*>(&As[kk][ty * 8]);
            float4 a1 = *reinterpret_cast<const float4*>(&As[kk][ty * 8 + 4]);
            float4 b0 = *reinterpret_cast<const float4*>(&Bs[kk][tx * 8]);
            float4 b1 = *reinterpret_cast<const float4*>(&Bs[kk][tx * 8 + 4]);
            a[0]=a0.x; a[1]=a0.y; a[2]=a0.z; a[3]=a0.w;
            a[4]=a1.x; a[5]=a1.y; a[6]=a1.z; a[7]=a1.w;
            b[0]=b0.x; b[1]=b0.y; b[2]=b0.z; b[3]=b0.w;
            b[4]=b1.x; b[5]=b1.y; b[6]=b1.z; b[7]=b1.w;
            #pragma unroll
            for (int i = 0; i < 8; i++)
                #pragma unroll
                for (int j = 0; j < 8; j++)
                    acc[i][j] += a[i] * b[j];
        }
        __syncthreads();
    }
    #pragma unroll
    for (int i = 0; i < 8; i++) {
        int gm = rowBase + ty * 8 + i;
        if (gm >= M) continue;
        #pragma unroll
        for (int j = 0; j < 8; j++) {
            int gn = colBase + tx * 8 + j;
            if (gn >= N) continue;
            float v = acc[i][j];
            if (bias) v += bias[gn];
            C[(size_t)gm * N + gn] = v;
        }
    }
}

__global__ __launch_bounds__(256) void gemm_in(const float* __restrict__ x) {
    gemm_body(x, g_Wcat, g_bias4, g_G, T_ * B_, N4, Fdim);
}

__global__ __launch_bounds__(256) void gemm_out(const float* __restrict__ fw,
                                                const float* __restrict__ fb,
                                                float* __restrict__ out) {
    gemm_body(g_Hbuf, fw, fb, out, T_ * B_, FO, H_);
}

// ---------------- two-level grid barrier ----------------
__device__ __forceinline__ void grid_barrier() {
    __syncthreads();
    __threadfence();   // release
    if (threadIdx.x == 0) {
        unsigned gen = g_gen;
        unsigned grp = blockIdx.x & (NGRP - 1);
        unsigned p = atomicAdd(&g_cnt1[grp * 32], 1u);
        if (p == GRPSZ - 1) {
            unsigned q = atomicAdd(&g_cnt2, 1u);
            if (q == NGRP - 1) {
                #pragma unroll
                for (int i = 0; i < NGRP; i++) g_cnt1[i * 32] = 0;
                g_cnt2 = 0;
                __threadfence();
                g_gen = gen + 1;
            }
        }
        while (g_gen == gen) { }
    }
    __syncthreads();
    __threadfence();   // acquire
}

// ---------------- persistent recurrence: all 128 steps in one launch ----------
__global__ __launch_bounds__(256, 2) void recurrence() {
    __shared__ float As[16][68];
    __shared__ float Bs[16][132];
    int tid = threadIdx.x;
    int tx = tid & 15, ty = tid >> 4;
    int nTile = blockIdx.x & 31;
    int s = blockIdx.x >> 5;
    int colBase = nTile * 128;
    int kbase = s * KCHUNK;
    // update-phase quad: spread across all 256 CTAs (64 quads per CTA)
    int q = blockIdx.x * 64 + (tid & 63);
    bool upd = tid < 64;
    float* preOut = g_preK + (size_t)s * B_ * N4;

    for (int t = 0; t < T_; t++) {
        // ======== phase 1: pre = h @ Ucat (64 x 128 tile, K chunk s)
        float acc[4][8];
        #pragma unroll
        for (int i = 0; i < 4; i++)
            #pragma unroll
            for (int j = 0; j < 8; j++) acc[i][j] = 0.f;

        for (int k0 = 0; k0 < KCHUNK; k0 += 16) {
            {   // A: 64x16 = 256 float4, one per thread (transposed store)
                int r = tid >> 2, c4 = (tid & 3) * 4;
                float4 v = *reinterpret_cast<const float4*>(
                    &g_h[(size_t)r * H_ + kbase + k0 + c4]);
                As[c4 + 0][r] = v.x;
                As[c4 + 1][r] = v.y;
                As[c4 + 2][r] = v.z;
                As[c4 + 3][r] = v.w;
            }
            #pragma unroll
            for (int i = 0; i < 2; i++) {   // B: 16x128 = 512 float4
                int lin = tid + i * 256;
                int kk = lin >> 5, c4 = (lin & 31) * 4;
                float4 v = *reinterpret_cast<const float4*>(
                    &g_Ucat[(size_t)(kbase + kk + k0) * N4 + colBase + c4]);
                *reinterpret_cast<float4*>(&Bs[kk][c4]) = v;
            }
            __syncthreads();
            #pragma unroll
            for (int kk = 0; kk < 16; kk++) {
                float4 av = *reinterpret_cast<const float4*>(&As[kk][ty * 4]);
                float4 b0 = *reinterpret_cast<const float4*>(&Bs[kk][tx * 8]);
                float4 b1 = *reinterpret_cast<const float4*>(&Bs[kk][tx * 8 + 4]);
                float a[4] = {av.x, av.y, av.z, av.w};
                float b[8] = {b0.x, b0.y, b0.z, b0.w, b1.x, b1.y, b1.z, b1.w};
                #pragma unroll
                for (int i = 0; i < 4; i++)
                    #pragma unroll
                    for (int j = 0; j < 8; j++)
                        acc[i][j] += a[i] * b[j];
            }
            __syncthreads();
        }
        #pragma unroll
        for (int i = 0; i < 4; i++) {
            int r = ty * 4 + i;
            float4 v0 = {acc[i][0], acc[i][1], acc[i][2], acc[i][3]};
            float4 v1 = {acc[i][4], acc[i][5], acc[i][6], acc[i][7]};
            *reinterpret_cast<float4*>(&preOut[(size_t)r * N4 + colBase + tx * 8])     = v0;
            *reinterpret_cast<float4*>(&preOut[(size_t)r * N4 + colBase + tx * 8 + 4]) = v1;
        }

        grid_barrier();

        // ======== phase 2: gates + state update (64 quads per CTA, all SMs)
        if (upd) {
            int b = q >> 8;                 // q / 256
            int j = (q & 255) * 4;
            const float* Gt = g_G + (size_t)((size_t)t * B_ + b) * N4;
            float4 pf = *reinterpret_cast<const float4*>(&Gt[0 * H_ + j]);
            float4 pi = *reinterpret_cast<const float4*>(&Gt[1 * H_ + j]);
            float4 po = *reinterpret_cast<const float4*>(&Gt[2 * H_ + j]);
            float4 pa = *reinterpret_cast<const float4*>(&Gt[3 * H_ + j]);
            #pragma unroll
            for (int sp = 0; sp < SPLITK; sp++) {
                const float* pk = g_preK + (size_t)sp * B_ * N4 + (size_t)b * N4;
                float4 vf = *reinterpret_cast<const float4*>(&pk[0 * H_ + j]);
                float4 vi = *reinterpret_cast<const float4*>(&pk[1 * H_ + j]);
                float4 vo = *reinterpret_cast<const float4*>(&pk[2 * H_ + j]);
                float4 va = *reinterpret_cast<const float4*>(&pk[3 * H_ + j]);
                pf.x += vf.x; pf.y += vf.y; pf.z += vf.z; pf.w += vf.w;
                pi.x += vi.x; pi.y += vi.y; pi.z += vi.z; pi.w += vi.w;
                po.x += vo.x; po.y += vo.y; po.z += vo.z; po.w += vo.w;
                pa.x += va.x; pa.y += va.y; pa.z += va.z; pa.w += va.w;
            }
            float fv[4] = {pf.x, pf.y, pf.z, pf.w};
            float iv[4] = {pi.x, pi.y, pi.z, pi.w};
            float ov[4] = {po.x, po.y, po.z, po.w};
            float av[4] = {pa.x, pa.y, pa.z, pa.w};
            size_t base = (size_t)b * H_ + j;
            float4 cprev = *reinterpret_cast<const float4*>(&g_c[base]);
            float cp[4] = {cprev.x, cprev.y, cprev.z, cprev.w};
            float cnv[4], hnv[4];
            #pragma unroll
            for (int qq = 0; qq < 4; qq++) {
                float ff = 1.f / (1.f + expf(-fv[qq]));
                float ii = 1.f / (1.f + expf(-iv[qq]));
                float oo = 1.f / (1.f + expf(-ov[qq]));
                float cc = ii * tanhf(av[qq]) + ff * cp[qq];
                cnv[qq] = cc;
                hnv[qq] = oo * tanhf(cc);
            }
            float4 cn = {cnv[0], cnv[1], cnv[2], cnv[3]};
            float4 hn = {hnv[0], hnv[1], hnv[2], hnv[3]};
            *reinterpret_cast<float4*>(&g_c[base]) = cn;
            *reinterpret_cast<float4*>(&g_h[base]) = hn;
            *reinterpret_cast<float4*>(&g_Hbuf[(size_t)t * B_ * H_ + base]) = hn;
        }

        grid_barrier();
    }
}

// ---------------- launch ----------------
extern "C" void kernel_launch(void* const* d_in, const int* in_sizes, int n_in,
                              void* d_out, int out_size) {
    const float* x    = (const float*)d_in[0];
    const float* wfxw = (const float*)d_in[1];
    const float* wfxb = (const float*)d_in[2];
    const float* wixw = (const float*)d_in[3];
    const float* wixb = (const float*)d_in[4];
    const float* woxw = (const float*)d_in[5];
    const float* woxb = (const float*)d_in[6];
    const float* wcxw = (const float*)d_in[7];
    const float* wcxb = (const float*)d_in[8];
    const float* ufhw = (const float*)d_in[9];
    const float* uihw = (const float*)d_in[10];
    const float* uohw = (const float*)d_in[11];
    const float* uchw = (const float*)d_in[12];
    const float* fcow = (const float*)d_in[13];
    const float* fcob = (const float*)d_in[14];
    float* out = (float*)d_out;

    init_state<<<(B_ * H_ + 255) / 256, 256>>>();
    build_W<<<(Fdim * N4 + 255) / 256, 256>>>(wfxw, wixw, woxw, wcxw);
    build_bias<<<(N4 + 255) / 256, 256>>>(wfxb, wixb, woxb, wcxb);
    build_U<<<(H_ * N4 + 255) / 256, 256>>>(ufhw, uihw, uohw, uchw);

    {   // input projections: G = x @ Wcat + bias (vectorized B path, N=4096)
        dim3 grid(N4 / 128, (T_ * B_) / 128);
        gemm_in<<<grid, 256>>>(x);
    }

    recurrence<<<NCTA, 256>>>();

    {   // output projection: out = Hbuf @ fco_w + fco_b
        dim3 grid((FO + 127) / 128, (T_ * B_) / 128);
        gemm_out<<<grid, 256>>>(fcow, fcob, out);
    }
}